// round 12
// baseline (speedup 1.0000x reference)
#include <cuda_runtime.h>

// Problem constants (fixed by setup_inputs)
#define F_DIM    16384
#define BINS     128
#define FEAT     (2*BINS + 1)     // 257
#define OUT_DIM  64

#define NTHREADS 512
#define NWARPS   (NTHREADS/32)    // 16
#define VPT      (F_DIM/NTHREADS) // 32 values per thread (8 float4)

extern __shared__ unsigned char smem_raw[];

// Fused: per-row histogram features + out[row] = feats . W^T + b
// One block per row. Feats never leave the block (smem); W is read via LDG
// and stays resident in L1D across the ~28 blocks each SM runs.
__global__ __launch_bounds__(NTHREADS, 2)
void hist_fused_kernel(const float* __restrict__ x,
                       const float* __restrict__ W,
                       const float* __restrict__ bias,
                       float* __restrict__ out)
{
    int*   s_hist  = (int*)smem_raw;                                   // 16*128*4 = 8192 B
    float* s_feats = (float*)(smem_raw + (size_t)NWARPS * BINS * 4);   // 257 f (pad to 260)
    float* s_wmin  = s_feats + 260;
    float* s_wmax  = s_wmin + NWARPS;

    const int t    = threadIdx.x;
    const int wid  = t >> 5;
    const int lane = t & 31;
    const int row  = blockIdx.x;

    // zero per-warp histograms
    #pragma unroll
    for (int i = t; i < NWARPS * BINS; i += NTHREADS) s_hist[i] = 0;

    // Pass A: stream row HBM -> registers (float4), track min/max in flight
    const float4* xr = (const float4*)(x + (size_t)row * F_DIM);
    float4 v[VPT / 4];
    float lmin =  3.402823e38f;
    float lmax = -3.402823e38f;
    #pragma unroll
    for (int k = 0; k < VPT / 4; k++) {
        v[k] = xr[t + k * NTHREADS];
        lmin = fminf(lmin, fminf(fminf(v[k].x, v[k].y), fminf(v[k].z, v[k].w)));
        lmax = fmaxf(lmax, fmaxf(fmaxf(v[k].x, v[k].y), fmaxf(v[k].z, v[k].w)));
    }
    // warp reduce min/max
    #pragma unroll
    for (int s = 16; s; s >>= 1) {
        lmin = fminf(lmin, __shfl_xor_sync(0xffffffffu, lmin, s));
        lmax = fmaxf(lmax, __shfl_xor_sync(0xffffffffu, lmax, s));
    }
    if (lane == 0) { s_wmin[wid] = lmin; s_wmax[wid] = lmax; }
    __syncthreads();

    // block min/max
    float mn = s_wmin[0], mx = s_wmax[0];
    #pragma unroll
    for (int i = 1; i < NWARPS; i++) {
        mn = fminf(mn, s_wmin[i]);
        mx = fmaxf(mx, s_wmax[i]);
    }
    const float width = mx - mn;
    const float scale = (width > 0.0f) ? ((float)BINS / width) : 0.0f;
    const float base  = -mn * scale;   // bin = (int)fmaf(v, scale, base)

    // Pass B: histogram straight from registers, per-warp privatized counters
    int* hw = s_hist + wid * BINS;
    #pragma unroll
    for (int k = 0; k < VPT / 4; k++) {
        int b0 = min(BINS - 1, (int)fmaf(v[k].x, scale, base));
        int b1 = min(BINS - 1, (int)fmaf(v[k].y, scale, base));
        int b2 = min(BINS - 1, (int)fmaf(v[k].z, scale, base));
        int b3 = min(BINS - 1, (int)fmaf(v[k].w, scale, base));
        atomicAdd(&hw[b0], 1);
        atomicAdd(&hw[b1], 1);
        atomicAdd(&hw[b2], 1);
        atomicAdd(&hw[b3], 1);
    }
    __syncthreads();

    // reduce per-warp histograms + emit feats row into SMEM
    if (t < BINS) {
        int c = 0;
        #pragma unroll
        for (int w = 0; w < NWARPS; w++) c += s_hist[w * BINS + t];
        s_feats[t] = (float)c * (1.0f / (float)F_DIM);   // density: sum == F exactly
    } else if (t < BINS + BINS + 1) {
        int i = t - BINS;
        s_feats[BINS + i] = mn + ((float)i * (1.0f / (float)BINS)) * width;
    }
    __syncthreads();

    // ---- fused GEMM tail: out[row][c] = feats . W[c] + bias[c] ----
    // warp wid handles cols 4*wid .. 4*wid+3; lanes split k = lane + 32j.
    // feats LDS conflict-free, W LDG coalesced (L1-resident after first block).
    float f[8];
    #pragma unroll
    for (int j = 0; j < 8; j++) f[j] = s_feats[lane + 32 * j];
    const float f8 = (lane == 0) ? s_feats[256] : 0.0f;

    #pragma unroll
    for (int cc = 0; cc < 4; cc++) {
        const int c = wid * 4 + cc;
        const float* wr = W + (size_t)c * FEAT;
        float acc = 0.0f;
        #pragma unroll
        for (int j = 0; j < 8; j++)
            acc = fmaf(f[j], __ldg(wr + lane + 32 * j), acc);
        if (lane == 0) acc = fmaf(f8, __ldg(wr + 256), acc);
        // warp reduce (fixed order -> deterministic)
        #pragma unroll
        for (int s = 16; s; s >>= 1)
            acc += __shfl_xor_sync(0xffffffffu, acc, s);
        if (lane == 0)
            out[(size_t)row * OUT_DIM + c] = acc + __ldg(bias + c);
    }
}

extern "C" void kernel_launch(void* const* d_in, const int* in_sizes, int n_in,
                              void* d_out, int out_size)
{
    const float* x = (const float*)d_in[0];
    const float* W = (const float*)d_in[1];
    const float* b = (const float*)d_in[2];
    float* out = (float*)d_out;

    const int B = in_sizes[0] / F_DIM;

    // smem: hist 8192 + feats 260*4 + 2*16*4 = 9360 B
    const size_t sm = (size_t)NWARPS * BINS * 4 + 260 * 4 + 2 * NWARPS * 4;

    cudaFuncSetAttribute(hist_fused_kernel,
                         cudaFuncAttributeMaxDynamicSharedMemorySize, (int)sm);

    hist_fused_kernel<<<B, NTHREADS, sm>>>(x, W, b, out);
}